// round 6
// baseline (speedup 1.0000x reference)
#include <cuda_runtime.h>
#include <cuda_bf16.h>
#include <cstdint>

// Problem constants
#define BB    4
#define SS    1024
#define HIDD  2048
#define HH    16
#define DD    128
#define CACHE 2048
#define LTOT  (CACHE + SS)   // 3072
#define MM    (BB * SS)      // 4096

// ---------------------------------------------------------------------------
// Scratch (device globals: allocation-guard safe)
// ---------------------------------------------------------------------------
__device__ float g_attn[MM * HIDD];  // [B,S,H,D] == [M, HID]

// bf16 hi/lo splits
__device__ __align__(16) __nv_bfloat16 g_xh[MM * HIDD],        g_xl[MM * HIDD];
__device__ __align__(16) __nv_bfloat16 g_wqh[3 * HIDD * HIDD], g_wql[3 * HIDD * HIDD];
__device__ __align__(16) __nv_bfloat16 g_wph[HIDD * HIDD],     g_wpl[HIDD * HIDD];
__device__ __align__(16) __nv_bfloat16 g_ah[MM * HIDD],        g_al[MM * HIDD];
// QKV outputs of K1, pre-split (Q pre-scaled), [B,H,S,D]
__device__ __align__(16) __nv_bfloat16 g_qh[MM * HIDD],  g_ql[MM * HIDD];
__device__ __align__(16) __nv_bfloat16 g_nkh[MM * HIDD], g_nkl[MM * HIDD];
__device__ __align__(16) __nv_bfloat16 g_nvh[MM * HIDD], g_nvl[MM * HIDD];
// cached KV pre-split, [CACHE,H,D]
__device__ __align__(16) __nv_bfloat16 g_ckh[CACHE * HH * DD], g_ckl[CACHE * HH * DD];
__device__ __align__(16) __nv_bfloat16 g_cvh[CACHE * HH * DD], g_cvl[CACHE * HH * DD];

// ---------------------------------------------------------------------------
// Helpers (compute_103-safe)
// ---------------------------------------------------------------------------
__device__ __forceinline__ uint32_t smem_u32(const void* p) {
    return (uint32_t)__cvta_generic_to_shared(p);
}

__device__ __forceinline__ void ldsm4(uint32_t* r, uint32_t addr) {
    asm volatile("ldmatrix.sync.aligned.m8n8.x4.shared.b16 {%0,%1,%2,%3}, [%4];"
                 : "=r"(r[0]), "=r"(r[1]), "=r"(r[2]), "=r"(r[3]) : "r"(addr));
}

__device__ __forceinline__ void ldsm4t(uint32_t* r, uint32_t addr) {
    asm volatile("ldmatrix.sync.aligned.m8n8.x4.trans.shared.b16 {%0,%1,%2,%3}, [%4];"
                 : "=r"(r[0]), "=r"(r[1]), "=r"(r[2]), "=r"(r[3]) : "r"(addr));
}

__device__ __forceinline__ void mma16816(float* c, const uint32_t* a,
                                         const uint32_t* b) {
    asm volatile(
        "mma.sync.aligned.m16n8k16.row.col.f32.bf16.bf16.f32 "
        "{%0,%1,%2,%3}, {%4,%5,%6,%7}, {%8,%9}, {%0,%1,%2,%3};"
        : "+f"(c[0]), "+f"(c[1]), "+f"(c[2]), "+f"(c[3])
        : "r"(a[0]), "r"(a[1]), "r"(a[2]), "r"(a[3]), "r"(b[0]), "r"(b[1]));
}

__device__ __forceinline__ void cp16(uint32_t dst, const void* src) {
    asm volatile("cp.async.cg.shared.global [%0], [%1], 16;"
                 :: "r"(dst), "l"(src) : "memory");
}
#define CP_COMMIT() asm volatile("cp.async.commit_group;" ::: "memory")
#define CP_WAIT1()  asm volatile("cp.async.wait_group 1;" ::: "memory")

__device__ __forceinline__ void split4(float4 v, uint2& hi, uint2& lo) {
    __nv_bfloat162 h01 = __float22bfloat162_rn(make_float2(v.x, v.y));
    __nv_bfloat162 h23 = __float22bfloat162_rn(make_float2(v.z, v.w));
    float2 f01 = __bfloat1622float2(h01);
    float2 f23 = __bfloat1622float2(h23);
    __nv_bfloat162 l01 = __float22bfloat162_rn(make_float2(v.x - f01.x, v.y - f01.y));
    __nv_bfloat162 l23 = __float22bfloat162_rn(make_float2(v.z - f23.x, v.w - f23.y));
    hi.x = *(uint32_t*)&h01; hi.y = *(uint32_t*)&h23;
    lo.x = *(uint32_t*)&l01; lo.y = *(uint32_t*)&l23;
}

__device__ __forceinline__ void split2(float x, float y, uint32_t& h, uint32_t& l) {
    __nv_bfloat162 hb = __float22bfloat162_rn(make_float2(x, y));
    float2 hf = __bfloat1622float2(hb);
    __nv_bfloat162 lb = __float22bfloat162_rn(make_float2(x - hf.x, y - hf.y));
    h = *(uint32_t*)&hb;
    l = *(uint32_t*)&lb;
}

__device__ __forceinline__ float fast_exp(float x) {
    float t = x * 1.4426950408889634f;
    t = fmaxf(t, -125.0f);
    float r = __fadd_rn(t, 12582912.0f);
    float f = __fsub_rn(t, __fsub_rn(r, 12582912.0f));
    float p = 1.3333558e-3f;
    p = fmaf(p, f, 9.6181291e-3f);
    p = fmaf(p, f, 5.5504109e-2f);
    p = fmaf(p, f, 2.4022651e-1f);
    p = fmaf(p, f, 6.9314718e-1f);
    p = fmaf(p, f, 1.0f);
    int n = __float_as_int(r) - 0x4B400000;
    return p * __int_as_float((n + 127) << 23);
}

// ---------------------------------------------------------------------------
// Split fp32 -> bf16 hi + lo
// ---------------------------------------------------------------------------
template <int WHICH>
__global__ __launch_bounds__(256) void k_split(const float* __restrict__ in, int n4) {
    int i = blockIdx.x * 256 + threadIdx.x;
    if (i >= n4) return;
    const float4* src;
    uint2* dh;
    uint2* dl;
    if (WHICH == 0) { src = (const float4*)in;     dh = (uint2*)g_xh;  dl = (uint2*)g_xl; }
    if (WHICH == 1) { src = (const float4*)in;     dh = (uint2*)g_wqh; dl = (uint2*)g_wql; }
    if (WHICH == 2) { src = (const float4*)in;     dh = (uint2*)g_wph; dl = (uint2*)g_wpl; }
    if (WHICH == 3) { src = (const float4*)g_attn; dh = (uint2*)g_ah;  dl = (uint2*)g_al; }
    uint2 hi, lo;
    split4(src[i], hi, lo);
    dh[i] = hi;
    dl[i] = lo;
}

// cached KV split: blockIdx.y 0 -> K, 1 -> V
__global__ __launch_bounds__(256) void k_splitkv(const float* __restrict__ ck,
                                                 const float* __restrict__ cv) {
    const int n4 = CACHE * HH * DD / 4;
    int i = blockIdx.x * 256 + threadIdx.x;
    if (i >= n4) return;
    const float4* src = (const float4*)(blockIdx.y ? cv : ck);
    uint2* dh = (uint2*)(blockIdx.y ? g_cvh : g_ckh);
    uint2* dl = (uint2*)(blockIdx.y ? g_cvl : g_ckl);
    uint2 hi, lo;
    split4(src[i], hi, lo);
    dh[i] = hi;
    dl[i] = lo;
}

// ---------------------------------------------------------------------------
// mma.sync split-fp32 GEMM. Pass-major MMA ordering (dep distance 16).
// ---------------------------------------------------------------------------
#define TILEB  (128 * 80)
#define STG    (4 * TILEB)
#define NIT    (HIDD / 32)

template <int MODE>
__global__ __launch_bounds__(256) void k_gemm_mma(const float* __restrict__ bias,
                                                  float* __restrict__ out)
{
    extern __shared__ __align__(128) char smem[];   // 2 * STG

    const __nv_bfloat16* __restrict__ Ah = MODE ? g_xh : g_ah;
    const __nv_bfloat16* __restrict__ Al = MODE ? g_xl : g_al;
    const __nv_bfloat16* __restrict__ Bh = MODE ? g_wqh : g_wph;
    const __nv_bfloat16* __restrict__ Bl = MODE ? g_wql : g_wpl;

    const int tid = threadIdx.x;
    const int wid = tid >> 5, lane = tid & 31;
    const int m0 = blockIdx.y * 128;
    const int n0 = blockIdx.x * 128;
    const int warp_m = wid & 1;
    const int warp_n = wid >> 1;

    const int lr = tid >> 2;
    const int lc = tid & 3;
    const size_t aoff0 = (size_t)(m0 + lr) * HIDD + lc * 8;
    const size_t aoff1 = (size_t)(m0 + 64 + lr) * HIDD + lc * 8;
    const size_t boff0 = (size_t)(n0 + lr) * HIDD + lc * 8;
    const size_t boff1 = (size_t)(n0 + 64 + lr) * HIDD + lc * 8;
    const int dst0 = lr * 80 + lc * 16;
    const int dst1 = (64 + lr) * 80 + lc * 16;

    auto issue = [&](int t, int slot) {
        const int kc = t * 32;
        uint32_t s0 = smem_u32(smem + slot * STG);
        cp16(s0 + 0 * TILEB + dst0, Ah + aoff0 + kc);
        cp16(s0 + 0 * TILEB + dst1, Ah + aoff1 + kc);
        cp16(s0 + 1 * TILEB + dst0, Al + aoff0 + kc);
        cp16(s0 + 1 * TILEB + dst1, Al + aoff1 + kc);
        cp16(s0 + 2 * TILEB + dst0, Bh + boff0 + kc);
        cp16(s0 + 2 * TILEB + dst1, Bh + boff1 + kc);
        cp16(s0 + 3 * TILEB + dst0, Bl + boff0 + kc);
        cp16(s0 + 3 * TILEB + dst1, Bl + boff1 + kc);
        CP_COMMIT();
    };

    const int arow_l = lane & 15;
    const int ac16   = lane >> 4;
    const int brow_l = (lane & 7) + (lane >> 4) * 8;
    const int bc16   = (lane >> 3) & 1;

    float acc[4][4][4];
#pragma unroll
    for (int mf = 0; mf < 4; mf++)
#pragma unroll
        for (int nf = 0; nf < 4; nf++)
#pragma unroll
            for (int c = 0; c < 4; c++) acc[mf][nf][c] = 0.f;

    issue(0, 0);
    issue(1, 1);

    for (int t = 0; t < NIT; t++) {
        CP_WAIT1();
        __syncthreads();

        const uint32_t sb = smem_u32(smem + (t & 1) * STG);
        const uint32_t sAh = sb;
        const uint32_t sAl = sb + TILEB;
        const uint32_t sBh = sb + 2 * TILEB;
        const uint32_t sBl = sb + 3 * TILEB;

#pragma unroll
        for (int kk = 0; kk < 2; kk++) {
            uint32_t ah[4][4], al[4][4], bh[2][4], bl[2][4];
            const int acol = (kk * 2 + ac16) * 16;
            const int bcol = (kk * 2 + bc16) * 16;
#pragma unroll
            for (int mf = 0; mf < 4; mf++) {
                const int row = warp_m * 64 + mf * 16 + arow_l;
                ldsm4(ah[mf], sAh + row * 80 + acol);
                ldsm4(al[mf], sAl + row * 80 + acol);
            }
#pragma unroll
            for (int nf2 = 0; nf2 < 2; nf2++) {
                const int row = warp_n * 32 + nf2 * 16 + brow_l;
                ldsm4(bh[nf2], sBh + row * 80 + bcol);
                ldsm4(bl[nf2], sBl + row * 80 + bcol);
            }
            // pass-major: 16 independent MMAs per pass
#pragma unroll
            for (int mf = 0; mf < 4; mf++)
#pragma unroll
                for (int nf = 0; nf < 4; nf++)
                    mma16816(acc[mf][nf], ah[mf], &bh[nf >> 1][(nf & 1) * 2]);
#pragma unroll
            for (int mf = 0; mf < 4; mf++)
#pragma unroll
                for (int nf = 0; nf < 4; nf++)
                    mma16816(acc[mf][nf], ah[mf], &bl[nf >> 1][(nf & 1) * 2]);
#pragma unroll
            for (int mf = 0; mf < 4; mf++)
#pragma unroll
                for (int nf = 0; nf < 4; nf++)
                    mma16816(acc[mf][nf], al[mf], &bh[nf >> 1][(nf & 1) * 2]);
        }

        if (t + 2 < NIT) {
            __syncthreads();
            issue(t + 2, t & 1);
        }
    }

    // epilogue
    const float qscale = 0.08838834764831845f;   // 1/sqrt(128)
#pragma unroll
    for (int mf = 0; mf < 4; mf++) {
#pragma unroll
        for (int nf = 0; nf < 4; nf++) {
            const int gm = m0 + warp_m * 64 + mf * 16 + (lane >> 2);
            const int dn = warp_n * 32 + nf * 8 + (lane & 3) * 2;
            const float b0 = __ldg(bias + n0 + dn);
            const float b1 = __ldg(bias + n0 + dn + 1);
            float x0 = acc[mf][nf][0] + b0, x1 = acc[mf][nf][1] + b1;
            float x2 = acc[mf][nf][2] + b0, x3 = acc[mf][nf][3] + b1;
            if (MODE == 0) {
                float* p0 = out + (size_t)gm * HIDD + n0 + dn;
                *(float2*)p0 = make_float2(x0, x1);
                *(float2*)(p0 + 8 * HIDD) = make_float2(x2, x3);
            } else {
                const int which = n0 >> 11;           // 0:q 1:k 2:v
                const int h = (n0 >> 7) & 15;
                if (which == 0) { x0 *= qscale; x1 *= qscale; x2 *= qscale; x3 *= qscale; }
                __nv_bfloat16* dh = (which == 0) ? g_qh : ((which == 1) ? g_nkh : g_nvh);
                __nv_bfloat16* dl = (which == 0) ? g_ql : ((which == 1) ? g_nkl : g_nvl);
                const int bb = gm >> 10, sq = gm & 1023;
                const size_t idx0 = ((((size_t)bb * HH + h) << 10) + sq) * DD + dn;
                const size_t idx1 = idx0 + 8 * DD;
                uint32_t h0, l0, h1, l1;
                split2(x0, x1, h0, l0);
                split2(x2, x3, h1, l1);
                *(uint32_t*)(dh + idx0) = h0;
                *(uint32_t*)(dl + idx0) = l0;
                *(uint32_t*)(dh + idx1) = h1;
                *(uint32_t*)(dl + idx1) = l1;
            }
        }
    }
}

// ---------------------------------------------------------------------------
// Flash attention on mma.sync, pre-split operands, 2-stage cp.async KV pipe.
// BQ=128 (8 warps x 16 rows), BKV=64, 256 threads.
// smem: Qh,Ql[128][272] + 2 stages of {Kh,Kl,Vh,Vl}[64][272] = 204 KB.
// ---------------------------------------------------------------------------
#define QSTRIDE 272
#define AQ_H   0
#define AQ_L   34816
#define AKV0   69632
#define KVST   69632
#define OFF_KH 0
#define OFF_KL 17408
#define OFF_VH 34816
#define OFF_VL 52224
#define A_TOT  208896
#define NTILE  (LTOT / 64)   // 48

__global__ __launch_bounds__(256) void k_attn_mma()
{
    extern __shared__ __align__(128) char sm[];
    const uint32_t sbase = smem_u32(sm);

    const int tid = threadIdx.x;
    const int wid = tid >> 5, lane = tid & 31;
    const int bh = blockIdx.y;
    const int b = bh >> 4, h = bh & 15;
    const int q0 = blockIdx.x * 128;

    // ---- Q tiles via cp.async (group 0) ----
    {
        const size_t qrow = ((size_t)bh * SS + q0) * DD;
#pragma unroll
        for (int i = 0; i < 8; i++) {
            int rem = tid + i * 256;          // 0..2047
            int row = rem >> 4, c = rem & 15;
            cp16(sbase + AQ_H + row * QSTRIDE + c * 16, g_qh + qrow + row * DD + c * 8);
        }
#pragma unroll
        for (int i = 0; i < 8; i++) {
            int rem = tid + i * 256;
            int row = rem >> 4, c = rem & 15;
            cp16(sbase + AQ_L + row * QSTRIDE + c * 16, g_ql + qrow + row * DD + c * 8);
        }
        CP_COMMIT();
    }

    const size_t newbase = (size_t)bh * SS * DD;

    auto issue_kv = [&](int t, int s) {
        const int kv0 = t * 64;
        const uint32_t sb = sbase + AKV0 + s * KVST;
#pragma unroll
        for (int i = 0; i < 4; i++) {
            int rem = tid + i * 256;          // 0..1023
            int row = rem >> 4, c = rem & 15;
            int kv = kv0 + row;
            const __nv_bfloat16* s1 = (kv < CACHE)
                ? (g_ckh + ((size_t)kv * HH + h) * DD)
                : (g_nkh + newbase + (size_t)(kv - CACHE) * DD);
            const __nv_bfloat16* s2 = (kv < CACHE)
                ? (g_ckl + ((size_t)kv * HH + h) * DD)
                : (g_nkl + newbase + (size_t)(kv - CACHE) * DD);
            const __nv_bfloat16* s3 = (kv < CACHE)
                ? (g_cvh + ((size_t)kv * HH + h) * DD)
                : (g_nvh + newbase + (size_t)(kv - CACHE) * DD);
            const __nv_bfloat16* s4 = (kv < CACHE)
                ? (g_cvl + ((size_t)kv * HH + h) * DD)
                : (g_nvl + newbase + (size_t)(kv - CACHE) * DD);
            const uint32_t d = row * QSTRIDE + c * 16;
            cp16(sb + OFF_KH + d, s1 + c * 8);
            cp16(sb + OFF_KL + d, s2 + c * 8);
            cp16(sb + OFF_VH + d, s3 + c * 8);
            cp16(sb + OFF_VL + d, s4 + c * 8);
        }
        CP_COMMIT();
    };

    issue_kv(0, 0);
    issue_kv(1, 1);

    // softmax state
    float m0 = -1e30f, m1 = -1e30f, l0 = 0.f, l1 = 0.f;
    float o[16][4];
#pragma unroll
    for (int nd = 0; nd < 16; nd++)
#pragma unroll
        for (int c = 0; c < 4; c++) o[nd][c] = 0.f;

    const int arow = lane & 15;
    const int ac16 = lane >> 4;
    const int brow = (lane & 7) + (lane >> 4) * 8;
    const int bc16 = (lane >> 3) & 1;
    const uint32_t qah = sbase + AQ_H + (wid * 16 + arow) * QSTRIDE + ac16 * 16;
    const uint32_t qal = sbase + AQ_L + (wid * 16 + arow) * QSTRIDE + ac16 * 16;
    const uint32_t vrow_addr = (lane & 15) * QSTRIDE + (lane >> 4) * 16;

    for (int t = 0; t < NTILE; t++) {
        CP_WAIT1();
        __syncthreads();
        const uint32_t kb = sbase + AKV0 + (t & 1) * KVST;

        // ---- S = Q @ K^T (pass-major, np pairs) ----
        float s[8][4];
#pragma unroll
        for (int nf = 0; nf < 8; nf++)
#pragma unroll
            for (int c = 0; c < 4; c++) s[nf][c] = 0.f;

#pragma unroll
        for (int ks = 0; ks < 8; ks++) {
            uint32_t qh[4], ql[4];
            ldsm4(qh, qah + ks * 32);
            ldsm4(ql, qal + ks * 32);
#pragma unroll
            for (int npp = 0; npp < 2; npp++) {
                uint32_t kh[2][4], kl[2][4];
#pragma unroll
                for (int p2 = 0; p2 < 2; p2++) {
                    const int np = npp * 2 + p2;
                    const uint32_t ka = (np * 16 + brow) * QSTRIDE + bc16 * 16 + ks * 32;
                    ldsm4(kh[p2], kb + OFF_KH + ka);
                    ldsm4(kl[p2], kb + OFF_KL + ka);
                }
#pragma unroll
                for (int p2 = 0; p2 < 2; p2++)
#pragma unroll
                    for (int j = 0; j < 2; j++)
                        mma16816(s[(npp * 2 + p2) * 2 + j], qh, &kh[p2][j * 2]);
#pragma unroll
                for (int p2 = 0; p2 < 2; p2++)
#pragma unroll
                    for (int j = 0; j < 2; j++)
                        mma16816(s[(npp * 2 + p2) * 2 + j], qh, &kl[p2][j * 2]);
#pragma unroll
                for (int p2 = 0; p2 < 2; p2++)
#pragma unroll
                    for (int j = 0; j < 2; j++)
                        mma16816(s[(npp * 2 + p2) * 2 + j], ql, &kh[p2][j * 2]);
            }
        }

        // ---- online softmax ----
        float mx0 = -1e30f, mx1 = -1e30f;
#pragma unroll
        for (int nf = 0; nf < 8; nf++) {
            mx0 = fmaxf(mx0, fmaxf(s[nf][0], s[nf][1]));
            mx1 = fmaxf(mx1, fmaxf(s[nf][2], s[nf][3]));
        }
        mx0 = fmaxf(mx0, __shfl_xor_sync(0xffffffffu, mx0, 1));
        mx0 = fmaxf(mx0, __shfl_xor_sync(0xffffffffu, mx0, 2));
        mx1 = fmaxf(mx1, __shfl_xor_sync(0xffffffffu, mx1, 1));
        mx1 = fmaxf(mx1, __shfl_xor_sync(0xffffffffu, mx1, 2));
        const float mn0 = fmaxf(m0, mx0);
        const float mn1 = fmaxf(m1, mx1);
        const float al0 = fast_exp(m0 - mn0);
        const float al1 = fast_exp(m1 - mn1);
        m0 = mn0; m1 = mn1;

        float sum0 = 0.f, sum1 = 0.f;
#pragma unroll
        for (int nf = 0; nf < 8; nf++) {
            s[nf][0] = fast_exp(s[nf][0] - mn0);
            s[nf][1] = fast_exp(s[nf][1] - mn0);
            s[nf][2] = fast_exp(s[nf][2] - mn1);
            s[nf][3] = fast_exp(s[nf][3] - mn1);
            sum0 += s[nf][0] + s[nf][1];
            sum1 += s[nf][2] + s[nf][3];
        }
        sum0 += __shfl_xor_sync(0xffffffffu, sum0, 1);
        sum0 += __shfl_xor_sync(0xffffffffu, sum0, 2);
        sum1 += __shfl_xor_sync(0xffffffffu, sum1, 1);
        sum1 += __shfl_xor_sync(0xffffffffu, sum1, 2);
        l0 = l0 * al0 + sum0;
        l1 = l1 * al1 + sum1;

#pragma unroll
        for (int nd = 0; nd < 16; nd++) {
            o[nd][0] *= al0; o[nd][1] *= al0;
            o[nd][2] *= al1; o[nd][3] *= al1;
        }

        // ---- pack P fragments ----
        uint32_t pah[4][4], pal[4][4];
#pragma unroll
        for (int np = 0; np < 4; np++) {
            split2(s[np * 2][0],     s[np * 2][1],     pah[np][0], pal[np][0]);
            split2(s[np * 2][2],     s[np * 2][3],     pah[np][1], pal[np][1]);
            split2(s[np * 2 + 1][0], s[np * 2 + 1][1], pah[np][2], pal[np][2]);
            split2(s[np * 2 + 1][2], s[np * 2 + 1][3], pah[np][3], pal[np][3]);
        }

        // ---- O += P @ V (pass-major, nd2 pairs) ----
#pragma unroll
        for (int ks = 0; ks < 4; ks++) {
#pragma unroll
            for (int nd4 = 0; nd4 < 4; nd4++) {
                uint32_t vh[2][4], vl[2][4];
#pragma unroll
                for (int p2 = 0; p2 < 2; p2++) {
                    const int nd2 = nd4 * 2 + p2;
                    const uint32_t va = (ks * 16) * QSTRIDE + nd2 * 32 + vrow_addr;
                    ldsm4t(vh[p2], kb + OFF_VH + va);
                    ldsm4t(vl[p2], kb + OFF_VL + va);
                }
#pragma unroll
                for (int p2 = 0; p2 < 2; p2++)
#pragma unroll
                    for (int j = 0; j < 2; j++)
                        mma16816(o[(nd4 * 2 + p2) * 2 + j], pah[ks], &vh[p2][j * 2]);
#pragma unroll
                for (int p2 = 0; p2 < 2; p2++)
#pragma unroll
                    for (int j = 0; j < 2; j++)
                        mma16816(o[(nd4 * 2 + p2) * 2 + j], pah[ks], &vl[p2][j * 2]);
#pragma unroll
                for (int p2 = 0; p2 < 2; p2++)
#pragma unroll
                    for (int j = 0; j < 2; j++)
                        mma16816(o[(nd4 * 2 + p2) * 2 + j], pal[ks], &vh[p2][j * 2]);
            }
        }

        __syncthreads();
        if (t + 2 < NTILE) issue_kv(t + 2, t & 1);
    }

    // ---- epilogue ----
    const float inv0 = __fdividef(1.0f, l0);
    const float inv1 = __fdividef(1.0f, l1);
    const int r0 = q0 + wid * 16 + (lane >> 2);
    const int r1 = r0 + 8;
#pragma unroll
    for (int nd = 0; nd < 16; nd++) {
        const int d = nd * 8 + (lane & 3) * 2;
        float2 w0 = {o[nd][0] * inv0, o[nd][1] * inv0};
        float2 w1 = {o[nd][2] * inv1, o[nd][3] * inv1};
        *(float2*)(g_attn + ((size_t)b * SS + r0) * HIDD + h * DD + d) = w0;
        *(float2*)(g_attn + ((size_t)b * SS + r1) * HIDD + h * DD + d) = w1;
    }
}

// ---------------------------------------------------------------------------
extern "C" void kernel_launch(void* const* d_in, const int* in_sizes, int n_in,
                              void* d_out, int out_size) {
    const float* x     = (const float*)d_in[0];
    const float* ck    = (const float*)d_in[1];
    const float* cv    = (const float*)d_in[2];
    const float* wqkv  = (const float*)d_in[3];
    const float* bqkv  = (const float*)d_in[4];
    const float* wproj = (const float*)d_in[5];
    const float* bproj = (const float*)d_in[6];
    float* out = (float*)d_out;

    // Splits
    {
        int n4x = MM * HIDD / 4;
        int n4q = 3 * HIDD * HIDD / 4;
        int n4p = HIDD * HIDD / 4;
        int n4c = CACHE * HH * DD / 4;
        k_split<0><<<(n4x + 255) / 256, 256>>>(x, n4x);
        k_split<1><<<(n4q + 255) / 256, 256>>>(wqkv, n4q);
        k_split<2><<<(n4p + 255) / 256, 256>>>(wproj, n4p);
        k_splitkv<<<dim3((n4c + 255) / 256, 2), 256>>>(ck, cv);
    }

    const int smem_gemm = 2 * STG;   // 81920

    // K1: QKV projection -> pre-split bf16 q/k/v [B,H,S,D]
    cudaFuncSetAttribute(k_gemm_mma<1>, cudaFuncAttributeMaxDynamicSharedMemorySize,
                         smem_gemm);
    k_gemm_mma<1><<<dim3(3 * HIDD / 128, MM / 128), 256, smem_gemm>>>(bqkv, nullptr);

    // K2: flash attention -> g_attn [B,S,H,D]
    cudaFuncSetAttribute(k_attn_mma, cudaFuncAttributeMaxDynamicSharedMemorySize,
                         A_TOT);
    k_attn_mma<<<dim3(SS / 128, BB * HH), 256, A_TOT>>>();

    // Split attention output for K3
    {
        int n4a = MM * HIDD / 4;
        k_split<3><<<(n4a + 255) / 256, 256>>>(nullptr, n4a);
    }

    // K3: output projection -> d_out
    cudaFuncSetAttribute(k_gemm_mma<0>, cudaFuncAttributeMaxDynamicSharedMemorySize,
                         smem_gemm);
    k_gemm_mma<0><<<dim3(HIDD / 128, MM / 128), 256, smem_gemm>>>(bproj, out);
}

// round 7
// speedup vs baseline: 1.4397x; 1.4397x over previous
#include <cuda_runtime.h>
#include <cuda_fp16.h>
#include <cstdint>

// Problem constants
#define BB    4
#define SS    1024
#define HIDD  2048
#define HH    16
#define DD    128
#define CACHE 2048
#define LTOT  (CACHE + SS)   // 3072
#define MM    (BB * SS)      // 4096

// ---------------------------------------------------------------------------
// Scratch (device globals). fp16 one-sided split: A-side hi only, B-side hi+lo.
// ---------------------------------------------------------------------------
__device__ __align__(16) __half g_xh[MM * HIDD];                       // x hi (A of K1)
__device__ __align__(16) __half g_wqh[3 * HIDD * HIDD], g_wql[3 * HIDD * HIDD];
__device__ __align__(16) __half g_wph[HIDD * HIDD],     g_wpl[HIDD * HIDD];
__device__ __align__(16) __half g_ah[MM * HIDD];                       // attn out hi (A of K3)
__device__ __align__(16) __half g_qh[MM * HIDD];                       // Q hi (pre-scaled)
__device__ __align__(16) __half g_nkh[MM * HIDD], g_nkl[MM * HIDD];    // new K hi+lo
__device__ __align__(16) __half g_nvh[MM * HIDD];                      // new V hi only
__device__ __align__(16) __half g_ckh[CACHE * HH * DD], g_ckl[CACHE * HH * DD];
__device__ __align__(16) __half g_cvh[CACHE * HH * DD];

// ---------------------------------------------------------------------------
// Helpers (compute_103-safe)
// ---------------------------------------------------------------------------
__device__ __forceinline__ uint32_t smem_u32(const void* p) {
    return (uint32_t)__cvta_generic_to_shared(p);
}

__device__ __forceinline__ void ldsm4(uint32_t* r, uint32_t addr) {
    asm volatile("ldmatrix.sync.aligned.m8n8.x4.shared.b16 {%0,%1,%2,%3}, [%4];"
                 : "=r"(r[0]), "=r"(r[1]), "=r"(r[2]), "=r"(r[3]) : "r"(addr));
}

__device__ __forceinline__ void ldsm4t(uint32_t* r, uint32_t addr) {
    asm volatile("ldmatrix.sync.aligned.m8n8.x4.trans.shared.b16 {%0,%1,%2,%3}, [%4];"
                 : "=r"(r[0]), "=r"(r[1]), "=r"(r[2]), "=r"(r[3]) : "r"(addr));
}

__device__ __forceinline__ void mma16816(float* c, const uint32_t* a,
                                         const uint32_t* b) {
    asm volatile(
        "mma.sync.aligned.m16n8k16.row.col.f32.f16.f16.f32 "
        "{%0,%1,%2,%3}, {%4,%5,%6,%7}, {%8,%9}, {%0,%1,%2,%3};"
        : "+f"(c[0]), "+f"(c[1]), "+f"(c[2]), "+f"(c[3])
        : "r"(a[0]), "r"(a[1]), "r"(a[2]), "r"(a[3]), "r"(b[0]), "r"(b[1]));
}

__device__ __forceinline__ void cp16(uint32_t dst, const void* src) {
    asm volatile("cp.async.cg.shared.global [%0], [%1], 16;"
                 :: "r"(dst), "l"(src) : "memory");
}
#define CP_COMMIT() asm volatile("cp.async.commit_group;" ::: "memory")
#define CP_WAIT1()  asm volatile("cp.async.wait_group 1;" ::: "memory")

// fp16 split helpers
__device__ __forceinline__ void split4h(float4 v, uint2& hi, uint2& lo) {
    __half2 h01 = __float22half2_rn(make_float2(v.x, v.y));
    __half2 h23 = __float22half2_rn(make_float2(v.z, v.w));
    float2 f01 = __half22float2(h01);
    float2 f23 = __half22float2(h23);
    __half2 l01 = __float22half2_rn(make_float2(v.x - f01.x, v.y - f01.y));
    __half2 l23 = __float22half2_rn(make_float2(v.z - f23.x, v.w - f23.y));
    hi.x = *(uint32_t*)&h01; hi.y = *(uint32_t*)&h23;
    lo.x = *(uint32_t*)&l01; lo.y = *(uint32_t*)&l23;
}
__device__ __forceinline__ uint2 pack4h(float4 v) {
    __half2 h01 = __float22half2_rn(make_float2(v.x, v.y));
    __half2 h23 = __float22half2_rn(make_float2(v.z, v.w));
    uint2 r;
    r.x = *(uint32_t*)&h01; r.y = *(uint32_t*)&h23;
    return r;
}
__device__ __forceinline__ void split2h(float x, float y, uint32_t& h, uint32_t& l) {
    __half2 hb = __float22half2_rn(make_float2(x, y));
    float2 hf = __half22float2(hb);
    __half2 lb = __float22half2_rn(make_float2(x - hf.x, y - hf.y));
    h = *(uint32_t*)&hb;
    l = *(uint32_t*)&lb;
}
__device__ __forceinline__ uint32_t pack2h(float x, float y) {
    __half2 hb = __float22half2_rn(make_float2(x, y));
    return *(uint32_t*)&hb;
}

__device__ __forceinline__ float fast_exp(float x) {
    float t = x * 1.4426950408889634f;
    t = fmaxf(t, -125.0f);
    float r = __fadd_rn(t, 12582912.0f);
    float f = __fsub_rn(t, __fsub_rn(r, 12582912.0f));
    float p = 1.3333558e-3f;
    p = fmaf(p, f, 9.6181291e-3f);
    p = fmaf(p, f, 5.5504109e-2f);
    p = fmaf(p, f, 2.4022651e-1f);
    p = fmaf(p, f, 6.9314718e-1f);
    p = fmaf(p, f, 1.0f);
    int n = __float_as_int(r) - 0x4B400000;
    return p * __int_as_float((n + 127) << 23);
}

// ---------------------------------------------------------------------------
// Input splits. WHICH 0: x -> hi only. 1: wqkv hi+lo. 2: wproj hi+lo.
// ---------------------------------------------------------------------------
template <int WHICH>
__global__ __launch_bounds__(256) void k_split(const float* __restrict__ in, int n4) {
    int i = blockIdx.x * 256 + threadIdx.x;
    if (i >= n4) return;
    const float4* src = (const float4*)in;
    if (WHICH == 0) {
        ((uint2*)g_xh)[i] = pack4h(src[i]);
    } else {
        uint2* dh = (WHICH == 1) ? (uint2*)g_wqh : (uint2*)g_wph;
        uint2* dl = (WHICH == 1) ? (uint2*)g_wql : (uint2*)g_wpl;
        uint2 hi, lo;
        split4h(src[i], hi, lo);
        dh[i] = hi;
        dl[i] = lo;
    }
}

// cached KV: y=0 -> K hi+lo, y=1 -> V hi only
__global__ __launch_bounds__(256) void k_splitkv(const float* __restrict__ ck,
                                                 const float* __restrict__ cv) {
    const int n4 = CACHE * HH * DD / 4;
    int i = blockIdx.x * 256 + threadIdx.x;
    if (i >= n4) return;
    if (blockIdx.y == 0) {
        uint2 hi, lo;
        split4h(((const float4*)ck)[i], hi, lo);
        ((uint2*)g_ckh)[i] = hi;
        ((uint2*)g_ckl)[i] = lo;
    } else {
        ((uint2*)g_cvh)[i] = pack4h(((const float4*)cv)[i]);
    }
}

// ---------------------------------------------------------------------------
// fp16 2-pass GEMM:  C = Ah*(Bh+Bl) + bias.  Tile 128x128, KC=32, 2-stage.
// smem per stage: Ah,Bh,Bl = 3 x 10240 B.
// ---------------------------------------------------------------------------
#define TILEB  (128 * 80)
#define STG    (3 * TILEB)
#define NIT    (HIDD / 32)

template <int MODE>
__global__ __launch_bounds__(256) void k_gemm_mma(const float* __restrict__ bias,
                                                  float* __restrict__ out)
{
    extern __shared__ __align__(128) char smem[];   // 2 * STG

    const __half* __restrict__ Ah = MODE ? g_xh : g_ah;
    const __half* __restrict__ Bh = MODE ? g_wqh : g_wph;
    const __half* __restrict__ Bl = MODE ? g_wql : g_wpl;

    const int tid = threadIdx.x;
    const int wid = tid >> 5, lane = tid & 31;
    const int m0 = blockIdx.y * 128;
    const int n0 = blockIdx.x * 128;
    const int warp_m = wid & 1;
    const int warp_n = wid >> 1;

    const int lr = tid >> 2;
    const int lc = tid & 3;
    const size_t aoff0 = (size_t)(m0 + lr) * HIDD + lc * 8;
    const size_t aoff1 = (size_t)(m0 + 64 + lr) * HIDD + lc * 8;
    const size_t boff0 = (size_t)(n0 + lr) * HIDD + lc * 8;
    const size_t boff1 = (size_t)(n0 + 64 + lr) * HIDD + lc * 8;
    const int dst0 = lr * 80 + lc * 16;
    const int dst1 = (64 + lr) * 80 + lc * 16;

    auto issue = [&](int t, int slot) {
        const int kc = t * 32;
        uint32_t s0 = smem_u32(smem + slot * STG);
        cp16(s0 + 0 * TILEB + dst0, Ah + aoff0 + kc);
        cp16(s0 + 0 * TILEB + dst1, Ah + aoff1 + kc);
        cp16(s0 + 1 * TILEB + dst0, Bh + boff0 + kc);
        cp16(s0 + 1 * TILEB + dst1, Bh + boff1 + kc);
        cp16(s0 + 2 * TILEB + dst0, Bl + boff0 + kc);
        cp16(s0 + 2 * TILEB + dst1, Bl + boff1 + kc);
        CP_COMMIT();
    };

    const int arow_l = lane & 15;
    const int ac16   = lane >> 4;
    const int brow_l = (lane & 7) + (lane >> 4) * 8;
    const int bc16   = (lane >> 3) & 1;

    float acc[4][4][4];
#pragma unroll
    for (int mf = 0; mf < 4; mf++)
#pragma unroll
        for (int nf = 0; nf < 4; nf++)
#pragma unroll
            for (int c = 0; c < 4; c++) acc[mf][nf][c] = 0.f;

    issue(0, 0);
    issue(1, 1);

    for (int t = 0; t < NIT; t++) {
        CP_WAIT1();
        __syncthreads();

        const uint32_t sb = smem_u32(smem + (t & 1) * STG);
        const uint32_t sAh = sb;
        const uint32_t sBh = sb + TILEB;
        const uint32_t sBl = sb + 2 * TILEB;

#pragma unroll
        for (int kk = 0; kk < 2; kk++) {
            uint32_t ah[4][4], bh[2][4], bl[2][4];
            const int acol = (kk * 2 + ac16) * 16;
            const int bcol = (kk * 2 + bc16) * 16;
#pragma unroll
            for (int mf = 0; mf < 4; mf++)
                ldsm4(ah[mf], sAh + (warp_m * 64 + mf * 16 + arow_l) * 80 + acol);
#pragma unroll
            for (int nf2 = 0; nf2 < 2; nf2++) {
                const int row = warp_n * 32 + nf2 * 16 + brow_l;
                ldsm4(bh[nf2], sBh + row * 80 + bcol);
                ldsm4(bl[nf2], sBl + row * 80 + bcol);
            }
#pragma unroll
            for (int mf = 0; mf < 4; mf++)
#pragma unroll
                for (int nf = 0; nf < 4; nf++)
                    mma16816(acc[mf][nf], ah[mf], &bh[nf >> 1][(nf & 1) * 2]);
#pragma unroll
            for (int mf = 0; mf < 4; mf++)
#pragma unroll
                for (int nf = 0; nf < 4; nf++)
                    mma16816(acc[mf][nf], ah[mf], &bl[nf >> 1][(nf & 1) * 2]);
        }

        if (t + 2 < NIT) {
            __syncthreads();
            issue(t + 2, t & 1);
        }
    }

    // epilogue
    const float qscale = 0.08838834764831845f;   // 1/sqrt(128)
#pragma unroll
    for (int mf = 0; mf < 4; mf++) {
#pragma unroll
        for (int nf = 0; nf < 4; nf++) {
            const int gm = m0 + warp_m * 64 + mf * 16 + (lane >> 2);
            const int dn = warp_n * 32 + nf * 8 + (lane & 3) * 2;
            const float b0 = __ldg(bias + n0 + dn);
            const float b1 = __ldg(bias + n0 + dn + 1);
            float x0 = acc[mf][nf][0] + b0, x1 = acc[mf][nf][1] + b1;
            float x2 = acc[mf][nf][2] + b0, x3 = acc[mf][nf][3] + b1;
            if (MODE == 0) {
                float* p0 = out + (size_t)gm * HIDD + n0 + dn;
                *(float2*)p0 = make_float2(x0, x1);
                *(float2*)(p0 + 8 * HIDD) = make_float2(x2, x3);
            } else {
                const int which = n0 >> 11;           // 0:q 1:k 2:v
                const int h = (n0 >> 7) & 15;
                const int bb = gm >> 10, sq = gm & 1023;
                const size_t idx0 = ((((size_t)bb * HH + h) << 10) + sq) * DD + dn;
                const size_t idx1 = idx0 + 8 * DD;
                if (which == 0) {
                    *(uint32_t*)(g_qh + idx0) = pack2h(x0 * qscale, x1 * qscale);
                    *(uint32_t*)(g_qh + idx1) = pack2h(x2 * qscale, x3 * qscale);
                } else if (which == 1) {
                    uint32_t h0, l0, h1, l1;
                    split2h(x0, x1, h0, l0);
                    split2h(x2, x3, h1, l1);
                    *(uint32_t*)(g_nkh + idx0) = h0;
                    *(uint32_t*)(g_nkl + idx0) = l0;
                    *(uint32_t*)(g_nkh + idx1) = h1;
                    *(uint32_t*)(g_nkl + idx1) = l1;
                } else {
                    *(uint32_t*)(g_nvh + idx0) = pack2h(x0, x1);
                    *(uint32_t*)(g_nvh + idx1) = pack2h(x2, x3);
                }
            }
        }
    }
}

// ---------------------------------------------------------------------------
// Flash attention (fp16): S = Qh*(Kh+Kl) (2-pass), O += Ph*Vh (1-pass).
// BQ=128, BKV=64, 256 threads. smem: Qh[128][272] + 2x{Kh,Kl,Vh}[64][272].
// ---------------------------------------------------------------------------
#define QSTRIDE 272
#define AQ_H   0
#define AKV0   34816
#define KVST   52224
#define OFF_KH 0
#define OFF_KL 17408
#define OFF_VH 34816
#define A_TOT  (34816 + 2 * 52224)   // 139264
#define NTILE  (LTOT / 64)           // 48

__global__ __launch_bounds__(256) void k_attn_mma()
{
    extern __shared__ __align__(128) char sm[];
    const uint32_t sbase = smem_u32(sm);

    const int tid = threadIdx.x;
    const int wid = tid >> 5, lane = tid & 31;
    const int bh = blockIdx.y;
    const int b = bh >> 4, h = bh & 15;
    const int q0 = blockIdx.x * 128;

    // ---- Q hi via cp.async ----
    {
        const size_t qrow = ((size_t)bh * SS + q0) * DD;
#pragma unroll
        for (int i = 0; i < 8; i++) {
            int rem = tid + i * 256;          // 0..2047
            int row = rem >> 4, c = rem & 15;
            cp16(sbase + AQ_H + row * QSTRIDE + c * 16, g_qh + qrow + row * DD + c * 8);
        }
        CP_COMMIT();
    }

    const size_t newbase = (size_t)bh * SS * DD;

    auto issue_kv = [&](int t, int s) {
        const int kv0 = t * 64;
        const uint32_t sb = sbase + AKV0 + s * KVST;
#pragma unroll
        for (int i = 0; i < 4; i++) {
            int rem = tid + i * 256;          // 0..1023
            int row = rem >> 4, c = rem & 15;
            int kv = kv0 + row;
            const __half* s1 = (kv < CACHE)
                ? (g_ckh + ((size_t)kv * HH + h) * DD)
                : (g_nkh + newbase + (size_t)(kv - CACHE) * DD);
            const __half* s2 = (kv < CACHE)
                ? (g_ckl + ((size_t)kv * HH + h) * DD)
                : (g_nkl + newbase + (size_t)(kv - CACHE) * DD);
            const __half* s3 = (kv < CACHE)
                ? (g_cvh + ((size_t)kv * HH + h) * DD)
                : (g_nvh + newbase + (size_t)(kv - CACHE) * DD);
            const uint32_t d = row * QSTRIDE + c * 16;
            cp16(sb + OFF_KH + d, s1 + c * 8);
            cp16(sb + OFF_KL + d, s2 + c * 8);
            cp16(sb + OFF_VH + d, s3 + c * 8);
        }
        CP_COMMIT();
    };

    issue_kv(0, 0);
    issue_kv(1, 1);

    float m0 = -1e30f, m1 = -1e30f, l0 = 0.f, l1 = 0.f;
    float o[16][4];
#pragma unroll
    for (int nd = 0; nd < 16; nd++)
#pragma unroll
        for (int c = 0; c < 4; c++) o[nd][c] = 0.f;

    const int arow = lane & 15;
    const int ac16 = lane >> 4;
    const int brow = (lane & 7) + (lane >> 4) * 8;
    const int bc16 = (lane >> 3) & 1;
    const uint32_t qah = sbase + AQ_H + (wid * 16 + arow) * QSTRIDE + ac16 * 16;
    const uint32_t vrow_addr = (lane & 15) * QSTRIDE + (lane >> 4) * 16;

    for (int t = 0; t < NTILE; t++) {
        CP_WAIT1();
        __syncthreads();
        const uint32_t kb = sbase + AKV0 + (t & 1) * KVST;

        // ---- S = Qh @ (Kh + Kl)^T ----
        float s[8][4];
#pragma unroll
        for (int nf = 0; nf < 8; nf++)
#pragma unroll
            for (int c = 0; c < 4; c++) s[nf][c] = 0.f;

#pragma unroll
        for (int ks = 0; ks < 8; ks++) {
            uint32_t qh[4];
            ldsm4(qh, qah + ks * 32);
#pragma unroll
            for (int npp = 0; npp < 2; npp++) {
                uint32_t kh[2][4], kl[2][4];
#pragma unroll
                for (int p2 = 0; p2 < 2; p2++) {
                    const int np = npp * 2 + p2;
                    const uint32_t ka = (np * 16 + brow) * QSTRIDE + bc16 * 16 + ks * 32;
                    ldsm4(kh[p2], kb + OFF_KH + ka);
                    ldsm4(kl[p2], kb + OFF_KL + ka);
                }
#pragma unroll
                for (int p2 = 0; p2 < 2; p2++)
#pragma unroll
                    for (int j = 0; j < 2; j++)
                        mma16816(s[(npp * 2 + p2) * 2 + j], qh, &kh[p2][j * 2]);
#pragma unroll
                for (int p2 = 0; p2 < 2; p2++)
#pragma unroll
                    for (int j = 0; j < 2; j++)
                        mma16816(s[(npp * 2 + p2) * 2 + j], qh, &kl[p2][j * 2]);
            }
        }

        // ---- online softmax ----
        float mx0 = -1e30f, mx1 = -1e30f;
#pragma unroll
        for (int nf = 0; nf < 8; nf++) {
            mx0 = fmaxf(mx0, fmaxf(s[nf][0], s[nf][1]));
            mx1 = fmaxf(mx1, fmaxf(s[nf][2], s[nf][3]));
        }
        mx0 = fmaxf(mx0, __shfl_xor_sync(0xffffffffu, mx0, 1));
        mx0 = fmaxf(mx0, __shfl_xor_sync(0xffffffffu, mx0, 2));
        mx1 = fmaxf(mx1, __shfl_xor_sync(0xffffffffu, mx1, 1));
        mx1 = fmaxf(mx1, __shfl_xor_sync(0xffffffffu, mx1, 2));
        const float mn0 = fmaxf(m0, mx0);
        const float mn1 = fmaxf(m1, mx1);
        const float al0 = fast_exp(m0 - mn0);
        const float al1 = fast_exp(m1 - mn1);
        m0 = mn0; m1 = mn1;

        float sum0 = 0.f, sum1 = 0.f;
#pragma unroll
        for (int nf = 0; nf < 8; nf++) {
            s[nf][0] = fast_exp(s[nf][0] - mn0);
            s[nf][1] = fast_exp(s[nf][1] - mn0);
            s[nf][2] = fast_exp(s[nf][2] - mn1);
            s[nf][3] = fast_exp(s[nf][3] - mn1);
            sum0 += s[nf][0] + s[nf][1];
            sum1 += s[nf][2] + s[nf][3];
        }
        sum0 += __shfl_xor_sync(0xffffffffu, sum0, 1);
        sum0 += __shfl_xor_sync(0xffffffffu, sum0, 2);
        sum1 += __shfl_xor_sync(0xffffffffu, sum1, 1);
        sum1 += __shfl_xor_sync(0xffffffffu, sum1, 2);
        l0 = l0 * al0 + sum0;
        l1 = l1 * al1 + sum1;

#pragma unroll
        for (int nd = 0; nd < 16; nd++) {
            o[nd][0] *= al0; o[nd][1] *= al0;
            o[nd][2] *= al1; o[nd][3] *= al1;
        }

        // ---- P hi fragments ----
        uint32_t pah[4][4];
#pragma unroll
        for (int np = 0; np < 4; np++) {
            pah[np][0] = pack2h(s[np * 2][0],     s[np * 2][1]);
            pah[np][1] = pack2h(s[np * 2][2],     s[np * 2][3]);
            pah[np][2] = pack2h(s[np * 2 + 1][0], s[np * 2 + 1][1]);
            pah[np][3] = pack2h(s[np * 2 + 1][2], s[np * 2 + 1][3]);
        }

        // ---- O += Ph @ Vh ----
#pragma unroll
        for (int ks = 0; ks < 4; ks++) {
#pragma unroll
            for (int nd4 = 0; nd4 < 4; nd4++) {
                uint32_t vh[2][4];
#pragma unroll
                for (int p2 = 0; p2 < 2; p2++) {
                    const int nd2 = nd4 * 2 + p2;
                    ldsm4t(vh[p2], kb + OFF_VH + (ks * 16) * QSTRIDE + nd2 * 32 + vrow_addr);
                }
#pragma unroll
                for (int p2 = 0; p2 < 2; p2++)
#pragma unroll
                    for (int j = 0; j < 2; j++)
                        mma16816(o[(nd4 * 2 + p2) * 2 + j], pah[ks], &vh[p2][j * 2]);
            }
        }

        __syncthreads();
        if (t + 2 < NTILE) issue_kv(t + 2, t & 1);
    }

    // ---- epilogue: normalize, write g_ah (fp16 hi, [B,S,H,D]) ----
    const float inv0 = __fdividef(1.0f, l0);
    const float inv1 = __fdividef(1.0f, l1);
    const int r0 = q0 + wid * 16 + (lane >> 2);
    const int r1 = r0 + 8;
#pragma unroll
    for (int nd = 0; nd < 16; nd++) {
        const int d = nd * 8 + (lane & 3) * 2;
        *(uint32_t*)(g_ah + ((size_t)b * SS + r0) * HIDD + h * DD + d) =
            pack2h(o[nd][0] * inv0, o[nd][1] * inv0);
        *(uint32_t*)(g_ah + ((size_t)b * SS + r1) * HIDD + h * DD + d) =
            pack2h(o[nd][2] * inv1, o[nd][3] * inv1);
    }
}

// ---------------------------------------------------------------------------
extern "C" void kernel_launch(void* const* d_in, const int* in_sizes, int n_in,
                              void* d_out, int out_size) {
    const float* x     = (const float*)d_in[0];
    const float* ck    = (const float*)d_in[1];
    const float* cv    = (const float*)d_in[2];
    const float* wqkv  = (const float*)d_in[3];
    const float* bqkv  = (const float*)d_in[4];
    const float* wproj = (const float*)d_in[5];
    const float* bproj = (const float*)d_in[6];
    float* out = (float*)d_out;

    // Splits
    {
        int n4x = MM * HIDD / 4;
        int n4q = 3 * HIDD * HIDD / 4;
        int n4p = HIDD * HIDD / 4;
        int n4c = CACHE * HH * DD / 4;
        k_split<0><<<(n4x + 255) / 256, 256>>>(x, n4x);
        k_split<1><<<(n4q + 255) / 256, 256>>>(wqkv, n4q);
        k_split<2><<<(n4p + 255) / 256, 256>>>(wproj, n4p);
        k_splitkv<<<dim3((n4c + 255) / 256, 2), 256>>>(ck, cv);
    }

    const int smem_gemm = 2 * STG;   // 61440

    // K1: QKV projection -> g_qh / g_nkh+l / g_nvh  [B,H,S,D]
    cudaFuncSetAttribute(k_gemm_mma<1>, cudaFuncAttributeMaxDynamicSharedMemorySize,
                         smem_gemm);
    k_gemm_mma<1><<<dim3(3 * HIDD / 128, MM / 128), 256, smem_gemm>>>(bqkv, nullptr);

    // K2: flash attention -> g_ah [B,S,H,D] (fp16)
    cudaFuncSetAttribute(k_attn_mma, cudaFuncAttributeMaxDynamicSharedMemorySize,
                         A_TOT);
    k_attn_mma<<<dim3(SS / 128, BB * HH), 256, A_TOT>>>();

    // K3: output projection -> d_out
    cudaFuncSetAttribute(k_gemm_mma<0>, cudaFuncAttributeMaxDynamicSharedMemorySize,
                         smem_gemm);
    k_gemm_mma<0><<<dim3(HIDD / 128, MM / 128), 256, smem_gemm>>>(bproj, out);
}